// round 1
// baseline (speedup 1.0000x reference)
#include <cuda_runtime.h>
#include <math.h>

#define T_TOK 1024
#define HDIM  2048
#define NEXP  8
#define TOPK  2
#define IMOE  1408
#define ISH   5632
#define GU_SH_N (2*ISH)    // 11264
#define GU_E_N  (2*IMOE)   // 2816
#define NPAIR (T_TOK*TOPK) // 2048

// ---------------- scratch (device globals: no allocations allowed) ----------------
__device__ float g_gu_sh[(size_t)T_TOK*GU_SH_N]; // 46 MB
__device__ float g_h_sh [(size_t)T_TOK*ISH];     // 23 MB
__device__ float g_gu_e [(size_t)NPAIR*GU_E_N];  // 23 MB
__device__ float g_h_e  [(size_t)NPAIR*IMOE];    // 11.5 MB
__device__ float g_sgate[T_TOK];
__device__ int   g_top_i[T_TOK*TOPK];
__device__ float g_top_w[T_TOK*TOPK];
__device__ int   g_cnt[NEXP];
__device__ int   g_off[NEXP];
__device__ int   g_fill[NEXP];
__device__ int   g_pair_tok[NPAIR];
__device__ float g_pair_w[NPAIR];

// ---------------- small kernels ----------------
__global__ void zero_kernel() {
    int i = threadIdx.x;
    if (i < NEXP) { g_cnt[i] = 0; g_fill[i] = 0; }
}

// one block per token; 9 warps: 8 router rows + 1 shared-gate row
__global__ void router_kernel(const float* __restrict__ x,
                              const float* __restrict__ gate_w,
                              const float* __restrict__ sgate_w) {
    int t = blockIdx.x;
    int w = threadIdx.x >> 5, lane = threadIdx.x & 31;
    __shared__ float logits[9];
    const float* xr = x + (size_t)t * HDIM;
    const float* wr = (w < 8) ? (gate_w + (size_t)w * HDIM) : sgate_w;
    float s = 0.f;
    for (int k = lane; k < HDIM; k += 32) s += xr[k] * wr[k];
    #pragma unroll
    for (int o = 16; o; o >>= 1) s += __shfl_xor_sync(0xffffffffu, s, o);
    if (lane == 0) logits[w] = s;
    __syncthreads();
    if (threadIdx.x == 0) {
        float mx = logits[0];
        #pragma unroll
        for (int e = 1; e < NEXP; e++) mx = fmaxf(mx, logits[e]);
        float p[NEXP], sum = 0.f;
        #pragma unroll
        for (int e = 0; e < NEXP; e++) { p[e] = expf(logits[e] - mx); sum += p[e]; }
        #pragma unroll
        for (int e = 0; e < NEXP; e++) p[e] /= sum;
        // top-2 with first-index tie-break (matches jax.lax.top_k)
        int i0 = 0; float v0 = p[0];
        #pragma unroll
        for (int e = 1; e < NEXP; e++) if (p[e] > v0) { v0 = p[e]; i0 = e; }
        int i1 = -1; float v1 = -1.f;
        #pragma unroll
        for (int e = 0; e < NEXP; e++) if (e != i0 && p[e] > v1) { v1 = p[e]; i1 = e; }
        float inv = 1.f / (v0 + v1);
        g_top_i[t*2+0] = i0; g_top_w[t*2+0] = v0 * inv;
        g_top_i[t*2+1] = i1; g_top_w[t*2+1] = v1 * inv;
        atomicAdd(&g_cnt[i0], 1);
        atomicAdd(&g_cnt[i1], 1);
        g_sgate[t] = 1.f / (1.f + expf(-logits[8]));
    }
}

__global__ void scan_kernel() {
    if (threadIdx.x == 0) {
        int o = 0;
        for (int e = 0; e < NEXP; e++) { g_off[e] = o; o += g_cnt[e]; }
    }
}

__global__ void scatter_kernel() {
    int t = blockIdx.x * blockDim.x + threadIdx.x;
    if (t >= T_TOK) return;
    #pragma unroll
    for (int k = 0; k < TOPK; k++) {
        int e = g_top_i[t*2+k];
        int pos = g_off[e] + atomicAdd(&g_fill[e], 1);
        g_pair_tok[pos] = t;
        g_pair_w[pos]   = g_top_w[t*2+k];
    }
}

__device__ __forceinline__ float silu_f(float v) { return v / (1.f + expf(-v)); }

__global__ void silu_sh_kernel() {
    int idx = blockIdx.x * blockDim.x + threadIdx.x;
    int n4 = T_TOK * (ISH/4);
    if (idx >= n4) return;
    int t = idx / (ISH/4), i4 = idx % (ISH/4);
    const float4 g = *(const float4*)&g_gu_sh[(size_t)t*GU_SH_N + i4*4];
    const float4 u = *(const float4*)&g_gu_sh[(size_t)t*GU_SH_N + ISH + i4*4];
    float4 r;
    r.x = silu_f(g.x)*u.x; r.y = silu_f(g.y)*u.y;
    r.z = silu_f(g.z)*u.z; r.w = silu_f(g.w)*u.w;
    *(float4*)&g_h_sh[(size_t)t*ISH + i4*4] = r;
}

__global__ void silu_e_kernel() {
    int idx = blockIdx.x * blockDim.x + threadIdx.x;
    int n4 = NPAIR * (IMOE/4);
    if (idx >= n4) return;
    int p = idx / (IMOE/4), i4 = idx % (IMOE/4);
    const float4 g = *(const float4*)&g_gu_e[(size_t)p*GU_E_N + i4*4];
    const float4 u = *(const float4*)&g_gu_e[(size_t)p*GU_E_N + IMOE + i4*4];
    float4 r;
    r.x = silu_f(g.x)*u.x; r.y = silu_f(g.y)*u.y;
    r.z = silu_f(g.z)*u.z; r.w = silu_f(g.w)*u.w;
    *(float4*)&g_h_e[(size_t)p*IMOE + i4*4] = r;
}

// ---------------- dense GEMM: C[M,N] = A[M,K] * B[N,K]^T, 128x128x8, 8x8/thread ----------------
// MODE 0: A=param(x), C=g_gu_sh.   MODE 1: A=g_h_sh, C=param(out), scaled by g_sgate[row].
template<int MODE>
__global__ __launch_bounds__(256) void gemm_dense(const float* __restrict__ Aparam,
                                                  const float* __restrict__ B,
                                                  float* __restrict__ Cparam,
                                                  int N, int K) {
    __shared__ float As[8][128];
    __shared__ float Bs[8][128];
    const float* A = (MODE == 0) ? Aparam : g_h_sh;
    float* C = (MODE == 0) ? g_gu_sh : Cparam;
    int tid = threadIdx.x;
    int bm = blockIdx.y * 128, bn = blockIdx.x * 128;
    int tr = tid >> 4, tc = tid & 15;
    int lrow = tid >> 1, lcol = (tid & 1) * 4;
    const float* Aptr = A + (size_t)(bm + lrow) * K + lcol;
    const float* Bptr = B + (size_t)(bn + lrow) * K + lcol;
    float acc[8][8] = {};
    for (int k0 = 0; k0 < K; k0 += 8) {
        float4 av = *(const float4*)(Aptr + k0);
        float4 bv = *(const float4*)(Bptr + k0);
        As[lcol+0][lrow]=av.x; As[lcol+1][lrow]=av.y; As[lcol+2][lrow]=av.z; As[lcol+3][lrow]=av.w;
        Bs[lcol+0][lrow]=bv.x; Bs[lcol+1][lrow]=bv.y; Bs[lcol+2][lrow]=bv.z; Bs[lcol+3][lrow]=bv.w;
        __syncthreads();
        #pragma unroll
        for (int k = 0; k < 8; k++) {
            float a[8], b[8];
            *(float4*)&a[0] = *(const float4*)&As[k][tr*8];
            *(float4*)&a[4] = *(const float4*)&As[k][tr*8+4];
            *(float4*)&b[0] = *(const float4*)&Bs[k][tc*8];
            *(float4*)&b[4] = *(const float4*)&Bs[k][tc*8+4];
            #pragma unroll
            for (int i = 0; i < 8; i++)
                #pragma unroll
                for (int j = 0; j < 8; j++)
                    acc[i][j] += a[i] * b[j];
        }
        __syncthreads();
    }
    #pragma unroll
    for (int i = 0; i < 8; i++) {
        int row = bm + tr*8 + i;
        float s = (MODE == 1) ? g_sgate[row] : 1.f;
        float4 c0 = make_float4(acc[i][0]*s, acc[i][1]*s, acc[i][2]*s, acc[i][3]*s);
        float4 c1 = make_float4(acc[i][4]*s, acc[i][5]*s, acc[i][6]*s, acc[i][7]*s);
        *(float4*)&C[(size_t)row*N + bn + tc*8]     = c0;
        *(float4*)&C[(size_t)row*N + bn + tc*8 + 4] = c1;
    }
}

// ---------------- expert gate_up: gathered-A GEMM -> g_gu_e ----------------
__global__ __launch_bounds__(256) void gemm_exp_gu(const float* __restrict__ x,
                                                   const float* __restrict__ w1) {
    int e = blockIdx.z;
    int cnt = g_cnt[e], off = g_off[e];
    int bm = blockIdx.y * 128;
    if (bm >= cnt) return;
    int bn = blockIdx.x * 128;
    const float* B = w1 + (size_t)e * GU_E_N * HDIM;
    __shared__ float As[8][128];
    __shared__ float Bs[8][128];
    int tid = threadIdx.x;
    int tr = tid >> 4, tc = tid & 15;
    int lrow = tid >> 1, lcol = (tid & 1) * 4;
    int m = bm + lrow;
    int p = off + min(m, cnt - 1);       // clamp: garbage rows never stored
    int tok = g_pair_tok[p];
    const float* Aptr = x + (size_t)tok * HDIM + lcol;
    const float* Bptr = B + (size_t)(bn + lrow) * HDIM + lcol;
    float acc[8][8] = {};
    for (int k0 = 0; k0 < HDIM; k0 += 8) {
        float4 av = *(const float4*)(Aptr + k0);
        float4 bv = *(const float4*)(Bptr + k0);
        As[lcol+0][lrow]=av.x; As[lcol+1][lrow]=av.y; As[lcol+2][lrow]=av.z; As[lcol+3][lrow]=av.w;
        Bs[lcol+0][lrow]=bv.x; Bs[lcol+1][lrow]=bv.y; Bs[lcol+2][lrow]=bv.z; Bs[lcol+3][lrow]=bv.w;
        __syncthreads();
        #pragma unroll
        for (int k = 0; k < 8; k++) {
            float a[8], b[8];
            *(float4*)&a[0] = *(const float4*)&As[k][tr*8];
            *(float4*)&a[4] = *(const float4*)&As[k][tr*8+4];
            *(float4*)&b[0] = *(const float4*)&Bs[k][tc*8];
            *(float4*)&b[4] = *(const float4*)&Bs[k][tc*8+4];
            #pragma unroll
            for (int i = 0; i < 8; i++)
                #pragma unroll
                for (int j = 0; j < 8; j++)
                    acc[i][j] += a[i] * b[j];
        }
        __syncthreads();
    }
    #pragma unroll
    for (int i = 0; i < 8; i++) {
        int mm = bm + tr*8 + i;
        if (mm < cnt) {
            float* Crow = &g_gu_e[(size_t)(off + mm) * GU_E_N + bn + tc*8];
            *(float4*)&Crow[0] = make_float4(acc[i][0],acc[i][1],acc[i][2],acc[i][3]);
            *(float4*)&Crow[4] = make_float4(acc[i][4],acc[i][5],acc[i][6],acc[i][7]);
        }
    }
}

// ---------------- expert down: GEMM on g_h_e segment, weighted atomicAdd into out ----------------
__global__ __launch_bounds__(256) void gemm_exp_down(const float* __restrict__ w2,
                                                     float* __restrict__ out) {
    int e = blockIdx.z;
    int cnt = g_cnt[e], off = g_off[e];
    int bm = blockIdx.y * 128;
    if (bm >= cnt) return;
    int bn = blockIdx.x * 128;
    const float* B = w2 + (size_t)e * HDIM * IMOE;
    __shared__ float As[8][128];
    __shared__ float Bs[8][128];
    int tid = threadIdx.x;
    int tr = tid >> 4, tc = tid & 15;
    int lrow = tid >> 1, lcol = (tid & 1) * 4;
    int m = bm + lrow;
    int pl = off + min(m, cnt - 1);
    const float* Aptr = g_h_e + (size_t)pl * IMOE + lcol;
    const float* Bptr = B + (size_t)(bn + lrow) * IMOE + lcol;
    float acc[8][8] = {};
    for (int k0 = 0; k0 < IMOE; k0 += 8) {
        float4 av = *(const float4*)(Aptr + k0);
        float4 bv = *(const float4*)(Bptr + k0);
        As[lcol+0][lrow]=av.x; As[lcol+1][lrow]=av.y; As[lcol+2][lrow]=av.z; As[lcol+3][lrow]=av.w;
        Bs[lcol+0][lrow]=bv.x; Bs[lcol+1][lrow]=bv.y; Bs[lcol+2][lrow]=bv.z; Bs[lcol+3][lrow]=bv.w;
        __syncthreads();
        #pragma unroll
        for (int k = 0; k < 8; k++) {
            float a[8], b[8];
            *(float4*)&a[0] = *(const float4*)&As[k][tr*8];
            *(float4*)&a[4] = *(const float4*)&As[k][tr*8+4];
            *(float4*)&b[0] = *(const float4*)&Bs[k][tc*8];
            *(float4*)&b[4] = *(const float4*)&Bs[k][tc*8+4];
            #pragma unroll
            for (int i = 0; i < 8; i++)
                #pragma unroll
                for (int j = 0; j < 8; j++)
                    acc[i][j] += a[i] * b[j];
        }
        __syncthreads();
    }
    #pragma unroll
    for (int i = 0; i < 8; i++) {
        int mm = bm + tr*8 + i;
        if (mm < cnt) {
            int p = off + mm;
            int tok = g_pair_tok[p];
            float pw = g_pair_w[p];
            float* orow = out + (size_t)tok * HDIM + bn + tc*8;
            #pragma unroll
            for (int j = 0; j < 8; j++)
                atomicAdd(&orow[j], pw * acc[i][j]);
        }
    }
}

// ---------------- launch ----------------
extern "C" void kernel_launch(void* const* d_in, const int* in_sizes, int n_in,
                              void* d_out, int out_size) {
    const float* x     = (const float*)d_in[0]; // [2,512,2048]
    const float* gatew = (const float*)d_in[1]; // [8,2048]
    const float* w1    = (const float*)d_in[2]; // [8,2816,2048]
    const float* w2    = (const float*)d_in[3]; // [8,2048,1408]
    const float* sgu   = (const float*)d_in[4]; // [11264,2048]
    const float* sdown = (const float*)d_in[5]; // [2048,5632]
    const float* sgw   = (const float*)d_in[6]; // [1,2048]
    float* out = (float*)d_out;                 // [2,512,2048]

    zero_kernel<<<1, 32>>>();
    router_kernel<<<T_TOK, 288>>>(x, gatew, sgw);
    scan_kernel<<<1, 32>>>();
    scatter_kernel<<<(T_TOK + 255) / 256, 256>>>();

    // shared expert: gate_up GEMM -> silu*mul -> down GEMM (writes out, scaled by sigmoid gate)
    gemm_dense<0><<<dim3(GU_SH_N/128, T_TOK/128), 256>>>(x, sgu, nullptr, GU_SH_N, HDIM);
    silu_sh_kernel<<<(T_TOK*(ISH/4) + 255) / 256, 256>>>();
    gemm_dense<1><<<dim3(HDIM/128, T_TOK/128), 256>>>(nullptr, sdown, out, HDIM, ISH);

    // sparse experts: gathered gate_up GEMM -> silu*mul -> down GEMM w/ weighted scatter-add
    gemm_exp_gu<<<dim3(GU_E_N/128, T_TOK/128, NEXP), 256>>>(x, w1);
    silu_e_kernel<<<(NPAIR*(IMOE/4) + 255) / 256, 256>>>();
    gemm_exp_down<<<dim3(HDIM/128, T_TOK/128, NEXP), 256>>>(w2, out);
}

// round 3
// speedup vs baseline: 2.5418x; 2.5418x over previous
#include <cuda_runtime.h>
#include <cuda_bf16.h>
#include <math.h>
#include <stdint.h>

#define T_TOK 1024
#define HDIM  2048
#define NEXP  8
#define TOPK  2
#define IMOE  1408
#define ISH   5632
#define NPAIR (T_TOK*TOPK)

// ---------------- scratch (device globals; allocations forbidden) ----------------
__device__ __nv_bfloat16 g_x_h [(size_t)T_TOK*HDIM],      g_x_l [(size_t)T_TOK*HDIM];
__device__ __nv_bfloat16 g_sgu_h[(size_t)2*ISH*HDIM],     g_sgu_l[(size_t)2*ISH*HDIM];
__device__ __nv_bfloat16 g_sdn_h[(size_t)HDIM*ISH],       g_sdn_l[(size_t)HDIM*ISH];
__device__ __nv_bfloat16 g_w1_h[(size_t)NEXP*2*IMOE*HDIM],g_w1_l[(size_t)NEXP*2*IMOE*HDIM];
__device__ __nv_bfloat16 g_w2_h[(size_t)NEXP*HDIM*IMOE],  g_w2_l[(size_t)NEXP*HDIM*IMOE];
__device__ __nv_bfloat16 g_hsh_h[(size_t)T_TOK*ISH],      g_hsh_l[(size_t)T_TOK*ISH];
__device__ __nv_bfloat16 g_xg_h[(size_t)NPAIR*HDIM],      g_xg_l[(size_t)NPAIR*HDIM];
__device__ __nv_bfloat16 g_he_h[(size_t)NPAIR*IMOE],      g_he_l[(size_t)NPAIR*IMOE];
__device__ float g_gu_sh[(size_t)T_TOK*2*ISH];   // fp32 gate_up scratch (shared)
__device__ float g_gu_e [(size_t)NPAIR*2*IMOE];  // fp32 gate_up scratch (experts)

__device__ float g_sgate[T_TOK];
__device__ int   g_top_i[T_TOK*TOPK];
__device__ float g_top_w[T_TOK*TOPK];
__device__ int   g_cnt[NEXP];
__device__ int   g_off[NEXP];
__device__ int   g_fill[NEXP];
__device__ int   g_pair_tok[NPAIR];
__device__ float g_pair_w[NPAIR];

// ---------------- mma/ldmatrix/cp.async helpers (base sm_103-legal PTX only) ----------------
__device__ __forceinline__ uint32_t smem_u32(const void* p) {
    uint32_t a;
    asm("{ .reg .u64 t; cvta.to.shared.u64 t, %1; cvt.u32.u64 %0, t; }" : "=r"(a) : "l"(p));
    return a;
}
#define LDMX4(r, addr) \
    asm volatile("ldmatrix.sync.aligned.m8n8.x4.shared.b16 {%0,%1,%2,%3}, [%4];" \
        : "=r"((r)[0]), "=r"((r)[1]), "=r"((r)[2]), "=r"((r)[3]) : "r"(addr))
#define MMA_BF16(c, a, b0, b1) \
    asm volatile("mma.sync.aligned.m16n8k16.row.col.f32.bf16.bf16.f32 " \
        "{%0,%1,%2,%3}, {%4,%5,%6,%7}, {%8,%9}, {%0,%1,%2,%3};" \
        : "+f"((c)[0]), "+f"((c)[1]), "+f"((c)[2]), "+f"((c)[3]) \
        : "r"((a)[0]), "r"((a)[1]), "r"((a)[2]), "r"((a)[3]), "r"(b0), "r"(b1))
#define CP_ASYNC16(dst, src) \
    asm volatile("cp.async.cg.shared.global [%0], [%1], 16;" :: "r"(dst), "l"(src))
#define CP_COMMIT() asm volatile("cp.async.commit_group;")
#define CP_WAIT(n)  asm volatile("cp.async.wait_group %0;" :: "n"(n))

// ---------------- GEMM geometry ----------------
#define BM 128
#define BN 128
#define BK 64
#define LDS_ST 72                      // bf16 elems per smem row (144 B, conflict-free ldmatrix)
#define TILE_BYTES (128*LDS_ST*2)      // 18432
#define STAGE_BYTES (4*TILE_BYTES)     // Ah, Al, Bh, Bl
#define SMEM_GEMM (2*STAGE_BYTES)      // 147456

__device__ __forceinline__ void cp_tile_a(uint32_t sdst, const __nv_bfloat16* g,
                                          int rowadd, int rowmax, int ld, int k0, int tid) {
    size_t gg = __cvta_generic_to_global(g);
    #pragma unroll
    for (int i = 0; i < 4; i++) {
        int chunk = tid + i*256;
        int row = chunk >> 3, c8 = chunk & 7;
        int gr = min(rowadd + row, rowmax);
        size_t src = gg + 2*((size_t)gr*ld + k0 + c8*8);
        uint32_t dst = sdst + row*144 + c8*16;
        CP_ASYNC16(dst, src);
    }
}
__device__ __forceinline__ void cp_tile_b(uint32_t sdst, const __nv_bfloat16* g,
                                          int row0, int ld, int k0, int tid) {
    size_t gg = __cvta_generic_to_global(g);
    #pragma unroll
    for (int i = 0; i < 4; i++) {
        int chunk = tid + i*256;
        int row = chunk >> 3, c8 = chunk & 7;
        size_t src = gg + 2*((size_t)(row0 + row)*ld + k0 + c8*8);
        uint32_t dst = sdst + row*144 + c8*16;
        CP_ASYNC16(dst, src);
    }
}

// MODE 0: store fp32 scratch C[row][col], ld=NB.
// MODE 1: out[row][col] = sgate[row]*acc  (NB==HDIM, dense)
// MODE 2: atomicAdd(out[tok][col], pair_w*acc)
template<int MODE, bool EXPERT>
__global__ __launch_bounds__(256) void gemm_mma(
    const __nv_bfloat16* __restrict__ Ah, const __nv_bfloat16* __restrict__ Al,
    const __nv_bfloat16* __restrict__ Bh, const __nv_bfloat16* __restrict__ Bl,
    float* __restrict__ Cout, int K, int NB)
{
    extern __shared__ char smem[];
    int tid = threadIdx.x;
    int bm = blockIdx.x * BM;
    int cnt = T_TOK, segoff = 0;
    if (EXPERT) {
        int e = blockIdx.z;
        cnt = g_cnt[e]; segoff = g_off[e];
        if (bm >= cnt) return;
        size_t eo = (size_t)e * (size_t)NB * (size_t)K;
        Bh += eo; Bl += eo;
    }
    int bn = blockIdx.y * BN;
    uint32_t sbase = smem_u32(smem);
    int rowA = segoff + bm, rowAmax = segoff + cnt - 1;
    int NC = K / BK;

    // preload stage 0
    {
        uint32_t tb = sbase;
        cp_tile_a(tb,              Ah, rowA, rowAmax, K, 0, tid);
        cp_tile_a(tb +   TILE_BYTES, Al, rowA, rowAmax, K, 0, tid);
        cp_tile_b(tb + 2*TILE_BYTES, Bh, bn, K, 0, tid);
        cp_tile_b(tb + 3*TILE_BYTES, Bl, bn, K, 0, tid);
        CP_COMMIT();
    }

    int lane = tid & 31, wid = tid >> 5;
    int wm = (wid >> 2) * 64, wn = (wid & 3) * 32;
    int lrow = lane & 15;
    int lcolb = ((lane >> 4) << 3) * 2;   // byte offset of 8-col group

    float acc[4][4][4] = {};

    for (int c = 0; c < NC; c++) {
        if (c + 1 < NC) {
            uint32_t tb = sbase + ((c + 1) & 1) * STAGE_BYTES;
            int k0 = (c + 1) * BK;
            cp_tile_a(tb,              Ah, rowA, rowAmax, K, k0, tid);
            cp_tile_a(tb +   TILE_BYTES, Al, rowA, rowAmax, K, k0, tid);
            cp_tile_b(tb + 2*TILE_BYTES, Bh, bn, K, k0, tid);
            cp_tile_b(tb + 3*TILE_BYTES, Bl, bn, K, k0, tid);
            CP_COMMIT();
            CP_WAIT(1);
        } else {
            CP_WAIT(0);
        }
        __syncthreads();

        uint32_t tb = sbase + (c & 1) * STAGE_BYTES;
        uint32_t sAh = tb, sAl = tb + TILE_BYTES;
        uint32_t sBh = tb + 2*TILE_BYTES, sBl = tb + 3*TILE_BYTES;

        #pragma unroll
        for (int kt = 0; kt < 4; kt++) {
            uint32_t cb = kt*32 + lcolb;   // kt*16 cols * 2B
            uint32_t a_h[4][4], a_l[4][4], b_h[2][4], b_l[2][4];
            #pragma unroll
            for (int mt = 0; mt < 4; mt++) {
                uint32_t off = (uint32_t)(wm + mt*16 + lrow)*144 + cb;
                LDMX4(a_h[mt], sAh + off);
                LDMX4(a_l[mt], sAl + off);
            }
            #pragma unroll
            for (int p = 0; p < 2; p++) {
                uint32_t off = (uint32_t)(wn + p*16 + lrow)*144 + cb;
                LDMX4(b_h[p], sBh + off);
                LDMX4(b_l[p], sBl + off);
            }
            #pragma unroll
            for (int mt = 0; mt < 4; mt++) {
                #pragma unroll
                for (int nt = 0; nt < 4; nt++) {
                    int p = nt >> 1, s = nt & 1;
                    MMA_BF16(acc[mt][nt], a_h[mt], b_h[p][s], b_h[p][s+2]);
                    MMA_BF16(acc[mt][nt], a_h[mt], b_l[p][s], b_l[p][s+2]);
                    MMA_BF16(acc[mt][nt], a_l[mt], b_h[p][s], b_h[p][s+2]);
                }
            }
        }
        __syncthreads();
    }

    // ---------------- epilogue ----------------
    int groupID = lane >> 2, qid = lane & 3;
    #pragma unroll
    for (int mt = 0; mt < 4; mt++) {
        #pragma unroll
        for (int half = 0; half < 2; half++) {
            int lr = bm + wm + mt*16 + groupID + half*8;   // row within segment
            if (lr >= cnt + bm - bm) { /* guard below */ }
            bool ok = (lr - bm) + bm < cnt ? (lr < cnt) : false;
            ok = (lr < cnt);
            if (!ok) continue;
            #pragma unroll
            for (int nt = 0; nt < 4; nt++) {
                int col = bn + wn + nt*8 + qid*2;
                float v0 = acc[mt][nt][half*2 + 0];
                float v1 = acc[mt][nt][half*2 + 1];
                if (MODE == 0) {
                    float2 v = make_float2(v0, v1);
                    *(float2*)&Cout[(size_t)(segoff + lr)*NB + col] = v;
                } else if (MODE == 1) {
                    float s = g_sgate[lr];
                    float2 v = make_float2(s*v0, s*v1);
                    *(float2*)&Cout[(size_t)lr*HDIM + col] = v;
                } else {
                    int p = segoff + lr;
                    int tok = g_pair_tok[p];
                    float w = g_pair_w[p];
                    atomicAdd(&Cout[(size_t)tok*HDIM + col],     w*v0);
                    atomicAdd(&Cout[(size_t)tok*HDIM + col + 1], w*v1);
                }
            }
        }
    }
}

// ---------------- elementwise kernels ----------------
__device__ __forceinline__ float silu_f(float v) { return v / (1.f + expf(-v)); }

// gu fp32 [rows, 2I] -> h = silu(g)*u -> bf16 hi/lo [rows, I]
__global__ void silu_split_kernel(const float* __restrict__ gu,
                                  __nv_bfloat16* __restrict__ Hh,
                                  __nv_bfloat16* __restrict__ Hl,
                                  int I, int rows) {
    int idx = blockIdx.x*blockDim.x + threadIdx.x;
    int n4 = rows * (I/4);
    if (idx >= n4) return;
    int r = idx / (I/4), c4 = idx % (I/4);
    const float4 g = *(const float4*)&gu[(size_t)r*2*I + c4*4];
    const float4 u = *(const float4*)&gu[(size_t)r*2*I + I + c4*4];
    float h0 = silu_f(g.x)*u.x, h1 = silu_f(g.y)*u.y;
    float h2 = silu_f(g.z)*u.z, h3 = silu_f(g.w)*u.w;
    __nv_bfloat16 a0 = __float2bfloat16(h0), a1 = __float2bfloat16(h1);
    __nv_bfloat16 a2 = __float2bfloat16(h2), a3 = __float2bfloat16(h3);
    size_t o = (size_t)r*I + c4*4;
    ((__nv_bfloat162*)(Hh + o))[0] = __nv_bfloat162(a0, a1);
    ((__nv_bfloat162*)(Hh + o))[1] = __nv_bfloat162(a2, a3);
    ((__nv_bfloat162*)(Hl + o))[0] = __nv_bfloat162(__float2bfloat16(h0 - __bfloat162float(a0)),
                                                    __float2bfloat16(h1 - __bfloat162float(a1)));
    ((__nv_bfloat162*)(Hl + o))[1] = __nv_bfloat162(__float2bfloat16(h2 - __bfloat162float(a2)),
                                                    __float2bfloat16(h3 - __bfloat162float(a3)));
}

__global__ void split_kernel(const float* __restrict__ src, __nv_bfloat16* __restrict__ hi,
                             __nv_bfloat16* __restrict__ lo, long n4) {
    long i = blockIdx.x*(long)blockDim.x + threadIdx.x;
    if (i >= n4) return;
    float4 v = ((const float4*)src)[i];
    __nv_bfloat16 h0 = __float2bfloat16(v.x), h1 = __float2bfloat16(v.y);
    __nv_bfloat16 h2 = __float2bfloat16(v.z), h3 = __float2bfloat16(v.w);
    __nv_bfloat162* H = (__nv_bfloat162*)(hi + 4*i);
    __nv_bfloat162* L = (__nv_bfloat162*)(lo + 4*i);
    H[0] = __nv_bfloat162(h0, h1); H[1] = __nv_bfloat162(h2, h3);
    L[0] = __nv_bfloat162(__float2bfloat16(v.x - __bfloat162float(h0)),
                          __float2bfloat16(v.y - __bfloat162float(h1)));
    L[1] = __nv_bfloat162(__float2bfloat16(v.z - __bfloat162float(h2)),
                          __float2bfloat16(v.w - __bfloat162float(h3)));
}

__global__ void gather_split_kernel(const float* __restrict__ x) {
    int i = blockIdx.x*blockDim.x + threadIdx.x;
    const int n4 = NPAIR * (HDIM/4);
    if (i >= n4) return;
    int p = i / (HDIM/4), c4 = i % (HDIM/4);
    int tok = g_pair_tok[p];
    float4 v = *(const float4*)(x + (size_t)tok*HDIM + c4*4);
    size_t o = (size_t)p*HDIM + c4*4;
    __nv_bfloat16 h0 = __float2bfloat16(v.x), h1 = __float2bfloat16(v.y);
    __nv_bfloat16 h2 = __float2bfloat16(v.z), h3 = __float2bfloat16(v.w);
    ((__nv_bfloat162*)(g_xg_h + o))[0] = __nv_bfloat162(h0, h1);
    ((__nv_bfloat162*)(g_xg_h + o))[1] = __nv_bfloat162(h2, h3);
    ((__nv_bfloat162*)(g_xg_l + o))[0] = __nv_bfloat162(__float2bfloat16(v.x - __bfloat162float(h0)),
                                                        __float2bfloat16(v.y - __bfloat162float(h1)));
    ((__nv_bfloat162*)(g_xg_l + o))[1] = __nv_bfloat162(__float2bfloat16(v.z - __bfloat162float(h2)),
                                                        __float2bfloat16(v.w - __bfloat162float(h3)));
}

// ---------------- router ----------------
__global__ void zero_kernel() {
    int i = threadIdx.x;
    if (i < NEXP) { g_cnt[i] = 0; g_fill[i] = 0; }
}
__global__ void router_kernel(const float* __restrict__ x,
                              const float* __restrict__ gate_w,
                              const float* __restrict__ sgate_w) {
    int t = blockIdx.x;
    int w = threadIdx.x >> 5, lane = threadIdx.x & 31;
    __shared__ float logits[9];
    const float* xr = x + (size_t)t * HDIM;
    const float* wr = (w < 8) ? (gate_w + (size_t)w * HDIM) : sgate_w;
    float s = 0.f;
    for (int k = lane; k < HDIM; k += 32) s += xr[k] * wr[k];
    #pragma unroll
    for (int o = 16; o; o >>= 1) s += __shfl_xor_sync(0xffffffffu, s, o);
    if (lane == 0) logits[w] = s;
    __syncthreads();
    if (threadIdx.x == 0) {
        float mx = logits[0];
        #pragma unroll
        for (int e = 1; e < NEXP; e++) mx = fmaxf(mx, logits[e]);
        float p[NEXP], sum = 0.f;
        #pragma unroll
        for (int e = 0; e < NEXP; e++) { p[e] = expf(logits[e] - mx); sum += p[e]; }
        #pragma unroll
        for (int e = 0; e < NEXP; e++) p[e] /= sum;
        int i0 = 0; float v0 = p[0];
        #pragma unroll
        for (int e = 1; e < NEXP; e++) if (p[e] > v0) { v0 = p[e]; i0 = e; }
        int i1 = -1; float v1 = -1.f;
        #pragma unroll
        for (int e = 0; e < NEXP; e++) if (e != i0 && p[e] > v1) { v1 = p[e]; i1 = e; }
        float inv = 1.f / (v0 + v1);
        g_top_i[t*2+0] = i0; g_top_w[t*2+0] = v0 * inv;
        g_top_i[t*2+1] = i1; g_top_w[t*2+1] = v1 * inv;
        atomicAdd(&g_cnt[i0], 1);
        atomicAdd(&g_cnt[i1], 1);
        g_sgate[t] = 1.f / (1.f + expf(-logits[8]));
    }
}
__global__ void scan_kernel() {
    if (threadIdx.x == 0) {
        int o = 0;
        for (int e = 0; e < NEXP; e++) { g_off[e] = o; o += g_cnt[e]; }
    }
}
__global__ void scatter_kernel() {
    int t = blockIdx.x * blockDim.x + threadIdx.x;
    if (t >= T_TOK) return;
    #pragma unroll
    for (int k = 0; k < TOPK; k++) {
        int e = g_top_i[t*2+k];
        int pos = g_off[e] + atomicAdd(&g_fill[e], 1);
        g_pair_tok[pos] = t;
        g_pair_w[pos]   = g_top_w[t*2+k];
    }
}

// ---------------- launch ----------------
static void* sym(const void* s) { void* p = nullptr; cudaGetSymbolAddress(&p, s); return p; }

extern "C" void kernel_launch(void* const* d_in, const int* in_sizes, int n_in,
                              void* d_out, int out_size) {
    const float* x     = (const float*)d_in[0];
    const float* gatew = (const float*)d_in[1];
    const float* w1    = (const float*)d_in[2];
    const float* w2    = (const float*)d_in[3];
    const float* sgu   = (const float*)d_in[4];
    const float* sdown = (const float*)d_in[5];
    const float* sgw   = (const float*)d_in[6];
    float* out = (float*)d_out;

    cudaFuncSetAttribute(gemm_mma<0,false>, cudaFuncAttributeMaxDynamicSharedMemorySize, SMEM_GEMM);
    cudaFuncSetAttribute(gemm_mma<1,false>, cudaFuncAttributeMaxDynamicSharedMemorySize, SMEM_GEMM);
    cudaFuncSetAttribute(gemm_mma<0,true>,  cudaFuncAttributeMaxDynamicSharedMemorySize, SMEM_GEMM);
    cudaFuncSetAttribute(gemm_mma<2,true>,  cudaFuncAttributeMaxDynamicSharedMemorySize, SMEM_GEMM);

    __nv_bfloat16 *xh = (__nv_bfloat16*)sym(g_x_h),  *xl = (__nv_bfloat16*)sym(g_x_l);
    __nv_bfloat16 *guh= (__nv_bfloat16*)sym(g_sgu_h),*gul= (__nv_bfloat16*)sym(g_sgu_l);
    __nv_bfloat16 *dnh= (__nv_bfloat16*)sym(g_sdn_h),*dnl= (__nv_bfloat16*)sym(g_sdn_l);
    __nv_bfloat16 *w1h= (__nv_bfloat16*)sym(g_w1_h), *w1l= (__nv_bfloat16*)sym(g_w1_l);
    __nv_bfloat16 *w2h= (__nv_bfloat16*)sym(g_w2_h), *w2l= (__nv_bfloat16*)sym(g_w2_l);
    __nv_bfloat16 *hsh= (__nv_bfloat16*)sym(g_hsh_h),*hsl= (__nv_bfloat16*)sym(g_hsh_l);
    __nv_bfloat16 *xgh= (__nv_bfloat16*)sym(g_xg_h), *xgl= (__nv_bfloat16*)sym(g_xg_l);
    __nv_bfloat16 *heh= (__nv_bfloat16*)sym(g_he_h), *hel= (__nv_bfloat16*)sym(g_he_l);
    float *gu_sh = (float*)sym(g_gu_sh);
    float *gu_e  = (float*)sym(g_gu_e);

    zero_kernel<<<1, 32>>>();
    router_kernel<<<T_TOK, 288>>>(x, gatew, sgw);
    scan_kernel<<<1, 32>>>();
    scatter_kernel<<<(T_TOK + 255) / 256, 256>>>();

    auto spl = [&](const float* s, __nv_bfloat16* h, __nv_bfloat16* l, long n) {
        long n4 = n / 4;
        split_kernel<<<(unsigned)((n4 + 255) / 256), 256>>>(s, h, l, n4);
    };
    spl(x,     xh,  xl,  (long)T_TOK*HDIM);
    spl(sgu,   guh, gul, (long)2*ISH*HDIM);
    spl(sdown, dnh, dnl, (long)HDIM*ISH);
    spl(w1,    w1h, w1l, (long)NEXP*2*IMOE*HDIM);
    spl(w2,    w2h, w2l, (long)NEXP*HDIM*IMOE);
    gather_split_kernel<<<(NPAIR*(HDIM/4) + 255) / 256, 256>>>(x);

    // shared expert: gate_up GEMM -> silu+resplit -> down GEMM (sigmoid-gated dense write)
    gemm_mma<0,false><<<dim3(T_TOK/BM, 2*ISH/BN), 256, SMEM_GEMM>>>(
        xh, xl, guh, gul, gu_sh, HDIM, 2*ISH);
    silu_split_kernel<<<(T_TOK*(ISH/4) + 255)/256, 256>>>(gu_sh, hsh, hsl, ISH, T_TOK);
    gemm_mma<1,false><<<dim3(T_TOK/BM, HDIM/BN), 256, SMEM_GEMM>>>(
        hsh, hsl, dnh, dnl, out, ISH, HDIM);

    // routed experts: gathered gate_up -> silu+resplit -> weighted down scatter-add
    gemm_mma<0,true><<<dim3(T_TOK/BM, 2*IMOE/BN, NEXP), 256, SMEM_GEMM>>>(
        xgh, xgl, w1h, w1l, gu_e, HDIM, 2*IMOE);
    silu_split_kernel<<<(NPAIR*(IMOE/4) + 255)/256, 256>>>(gu_e, heh, hel, IMOE, NPAIR);
    gemm_mma<2,true><<<dim3(T_TOK/BM, HDIM/BN, NEXP), 256, SMEM_GEMM>>>(
        heh, hel, w2h, w2l, out, IMOE, HDIM);
}

// round 4
// speedup vs baseline: 2.6740x; 1.0520x over previous
#include <cuda_runtime.h>
#include <cuda_bf16.h>
#include <math.h>
#include <stdint.h>

#define T_TOK 1024
#define HDIM  2048
#define NEXP  8
#define TOPK  2
#define IMOE  1408
#define ISH   5632
#define NPAIR (T_TOK*TOPK)

// ---------------- scratch (device globals; allocations forbidden) ----------------
__device__ __nv_bfloat16 g_x_h [(size_t)T_TOK*HDIM],      g_x_l [(size_t)T_TOK*HDIM];
__device__ __nv_bfloat16 g_sgu_h[(size_t)2*ISH*HDIM],     g_sgu_l[(size_t)2*ISH*HDIM];
__device__ __nv_bfloat16 g_sdn_h[(size_t)HDIM*ISH],       g_sdn_l[(size_t)HDIM*ISH];
__device__ __nv_bfloat16 g_w1_h[(size_t)NEXP*2*IMOE*HDIM],g_w1_l[(size_t)NEXP*2*IMOE*HDIM];
__device__ __nv_bfloat16 g_w2_h[(size_t)NEXP*HDIM*IMOE],  g_w2_l[(size_t)NEXP*HDIM*IMOE];
__device__ __nv_bfloat16 g_hsh_h[(size_t)T_TOK*ISH],      g_hsh_l[(size_t)T_TOK*ISH];
__device__ __nv_bfloat16 g_xg_h[(size_t)NPAIR*HDIM],      g_xg_l[(size_t)NPAIR*HDIM];
__device__ __nv_bfloat16 g_he_h[(size_t)NPAIR*IMOE],      g_he_l[(size_t)NPAIR*IMOE];

__device__ float g_sgate[T_TOK];
__device__ int   g_top_i[T_TOK*TOPK];
__device__ float g_top_w[T_TOK*TOPK];
__device__ int   g_cnt[NEXP];
__device__ int   g_off[NEXP];
__device__ int   g_fill[NEXP];
__device__ int   g_pair_tok[NPAIR];
__device__ float g_pair_w[NPAIR];

// ---------------- ptx helpers (base sm_103-legal only) ----------------
__device__ __forceinline__ uint32_t smem_u32(const void* p) {
    uint32_t a;
    asm("{ .reg .u64 t; cvta.to.shared.u64 t, %1; cvt.u32.u64 %0, t; }" : "=r"(a) : "l"(p));
    return a;
}
#define LDMX4(r, addr) \
    asm volatile("ldmatrix.sync.aligned.m8n8.x4.shared.b16 {%0,%1,%2,%3}, [%4];" \
        : "=r"((r)[0]), "=r"((r)[1]), "=r"((r)[2]), "=r"((r)[3]) : "r"(addr))
#define MMA_BF16(c, a, b0, b1) \
    asm volatile("mma.sync.aligned.m16n8k16.row.col.f32.bf16.bf16.f32 " \
        "{%0,%1,%2,%3}, {%4,%5,%6,%7}, {%8,%9}, {%0,%1,%2,%3};" \
        : "+f"((c)[0]), "+f"((c)[1]), "+f"((c)[2]), "+f"((c)[3]) \
        : "r"((a)[0]), "r"((a)[1]), "r"((a)[2]), "r"((a)[3]), "r"(b0), "r"(b1))
#define CP_ASYNC16(dst, src) \
    asm volatile("cp.async.cg.shared.global [%0], [%1], 16;" :: "r"(dst), "l"(src))
#define CP_COMMIT() asm volatile("cp.async.commit_group;")
#define CP_WAIT(n)  asm volatile("cp.async.wait_group %0;" :: "n"(n))

// ---------------- tile loaders (row stride 144B, conflict-free ldmatrix) ----------------
__device__ __forceinline__ void cp_tile128(uint32_t sdst, const __nv_bfloat16* g,
                                           int row0, int ld, int k0, int tid) {
    size_t gg = __cvta_generic_to_global(g);
    #pragma unroll
    for (int i = 0; i < 4; i++) {
        int chunk = tid + i*256;
        int row = chunk >> 3, c8 = chunk & 7;
        size_t src = gg + 2*((size_t)(row0 + row)*ld + k0 + c8*8);
        CP_ASYNC16(sdst + row*144 + c8*16, src);
    }
}
__device__ __forceinline__ void cp_tile128_clamp(uint32_t sdst, const __nv_bfloat16* g,
                                                 int rowadd, int rowmax, int ld, int k0, int tid) {
    size_t gg = __cvta_generic_to_global(g);
    #pragma unroll
    for (int i = 0; i < 4; i++) {
        int chunk = tid + i*256;
        int row = chunk >> 3, c8 = chunk & 7;
        int gr = min(rowadd + row, rowmax);
        size_t src = gg + 2*((size_t)gr*ld + k0 + c8*8);
        CP_ASYNC16(sdst + row*144 + c8*16, src);
    }
}
__device__ __forceinline__ void cp_tile64_clamp(uint32_t sdst, const __nv_bfloat16* g,
                                                int rowadd, int rowmax, int ld, int k0, int tid) {
    size_t gg = __cvta_generic_to_global(g);
    #pragma unroll
    for (int i = 0; i < 2; i++) {
        int chunk = tid + i*256;
        int row = chunk >> 3, c8 = chunk & 7;
        int gr = min(rowadd + row, rowmax);
        size_t src = gg + 2*((size_t)gr*ld + k0 + c8*8);
        CP_ASYNC16(sdst + row*144 + c8*16, src);
    }
}

#define BK 64
#define A_TILE_GU 9216          // 64*144
#define B_TILE    18432         // 128*144
#define STAGE_GU  (2*A_TILE_GU + 4*B_TILE)   // 92160
#define SMEM_GU   (2*STAGE_GU)               // 184320, 2 stages
#define STAGE_DN  (4*B_TILE)                 // 73728
#define SMEM_DN   (3*STAGE_DN)               // 221184, 3 stages

__device__ __forceinline__ float silu_f(float v) { return v / (1.f + expf(-v)); }

// ============ paired gate_up GEMM + fused SiLU + bf16 hi/lo split ============
// BM=64 rows, 128 h-cols per CTA (gate tile @ B rows bn, up tile @ B rows Nhalf+bn).
template<bool EXPERT>
__global__ __launch_bounds__(256) void gemm_gu(
    const __nv_bfloat16* __restrict__ Ah, const __nv_bfloat16* __restrict__ Al,
    const __nv_bfloat16* __restrict__ Bh, const __nv_bfloat16* __restrict__ Bl,
    __nv_bfloat16* __restrict__ Hh, __nv_bfloat16* __restrict__ Hl,
    int K, int Nhalf)
{
    extern __shared__ char smem[];
    int tid = threadIdx.x;
    int bm = blockIdx.x * 64;
    int cnt = T_TOK, segoff = 0;
    if (EXPERT) {
        int e = blockIdx.z;
        cnt = g_cnt[e]; segoff = g_off[e];
        if (bm >= cnt) return;
        size_t eo = (size_t)e * (size_t)(2*Nhalf) * (size_t)K;
        Bh += eo; Bl += eo;
    }
    int bn = blockIdx.y * 128;
    uint32_t sbase = smem_u32(smem);
    int rowA = segoff + bm, rowAmax = segoff + cnt - 1;
    int NC = K / BK;

    // stage offsets
    auto stage_load = [&](uint32_t tb, int k0) {
        cp_tile64_clamp(tb,                Ah, rowA, rowAmax, K, k0, tid);
        cp_tile64_clamp(tb + A_TILE_GU,    Al, rowA, rowAmax, K, k0, tid);
        cp_tile128(tb + 2*A_TILE_GU,             Bh, bn,          K, k0, tid);
        cp_tile128(tb + 2*A_TILE_GU +   B_TILE,  Bl, bn,          K, k0, tid);
        cp_tile128(tb + 2*A_TILE_GU + 2*B_TILE,  Bh, Nhalf + bn,  K, k0, tid);
        cp_tile128(tb + 2*A_TILE_GU + 3*B_TILE,  Bl, Nhalf + bn,  K, k0, tid);
    };
    stage_load(sbase, 0);
    CP_COMMIT();

    int lane = tid & 31, wid = tid >> 5;
    int wm = (wid & 1) * 32, wn = (wid >> 1) * 32;
    int lrow = lane & 15;
    int lcolb = (lane >> 4) * 16;

    float accg[2][4][4] = {}, accu[2][4][4] = {};

    for (int c = 0; c < NC; c++) {
        if (c + 1 < NC) {
            stage_load(sbase + ((c + 1) & 1) * STAGE_GU, (c + 1) * BK);
            CP_COMMIT();
            CP_WAIT(1);
        } else {
            CP_WAIT(0);
        }
        __syncthreads();

        uint32_t tb = sbase + (c & 1) * STAGE_GU;
        uint32_t sAh = tb, sAl = tb + A_TILE_GU;
        uint32_t sGh = tb + 2*A_TILE_GU,            sGl = sGh + B_TILE;
        uint32_t sUh = tb + 2*A_TILE_GU + 2*B_TILE, sUl = sUh + B_TILE;

        #pragma unroll
        for (int kt = 0; kt < 4; kt++) {
            uint32_t cb = kt*32 + lcolb;
            uint32_t a_h[2][4], a_l[2][4];
            #pragma unroll
            for (int mt = 0; mt < 2; mt++) {
                uint32_t off = (uint32_t)(wm + mt*16 + lrow)*144 + cb;
                LDMX4(a_h[mt], sAh + off);
                LDMX4(a_l[mt], sAl + off);
            }
            {
                uint32_t b_h[2][4], b_l[2][4];
                #pragma unroll
                for (int p = 0; p < 2; p++) {
                    uint32_t off = (uint32_t)(wn + p*16 + lrow)*144 + cb;
                    LDMX4(b_h[p], sGh + off);
                    LDMX4(b_l[p], sGl + off);
                }
                #pragma unroll
                for (int mt = 0; mt < 2; mt++)
                    #pragma unroll
                    for (int nt = 0; nt < 4; nt++) {
                        int p = nt >> 1, s = nt & 1;
                        MMA_BF16(accg[mt][nt], a_h[mt], b_h[p][s], b_h[p][s+2]);
                        MMA_BF16(accg[mt][nt], a_h[mt], b_l[p][s], b_l[p][s+2]);
                        MMA_BF16(accg[mt][nt], a_l[mt], b_h[p][s], b_h[p][s+2]);
                    }
            }
            {
                uint32_t b_h[2][4], b_l[2][4];
                #pragma unroll
                for (int p = 0; p < 2; p++) {
                    uint32_t off = (uint32_t)(wn + p*16 + lrow)*144 + cb;
                    LDMX4(b_h[p], sUh + off);
                    LDMX4(b_l[p], sUl + off);
                }
                #pragma unroll
                for (int mt = 0; mt < 2; mt++)
                    #pragma unroll
                    for (int nt = 0; nt < 4; nt++) {
                        int p = nt >> 1, s = nt & 1;
                        MMA_BF16(accu[mt][nt], a_h[mt], b_h[p][s], b_h[p][s+2]);
                        MMA_BF16(accu[mt][nt], a_h[mt], b_l[p][s], b_l[p][s+2]);
                        MMA_BF16(accu[mt][nt], a_l[mt], b_h[p][s], b_h[p][s+2]);
                    }
            }
        }
        __syncthreads();
    }

    // fused epilogue: h = silu(g)*u, split to bf16 hi/lo, direct store
    int groupID = lane >> 2, qid = lane & 3;
    #pragma unroll
    for (int mt = 0; mt < 2; mt++) {
        #pragma unroll
        for (int half = 0; half < 2; half++) {
            int r = wm + mt*16 + groupID + half*8;
            if (bm + r >= cnt) continue;
            size_t rowoff = (size_t)(segoff + bm + r) * (size_t)Nhalf;
            #pragma unroll
            for (int nt = 0; nt < 4; nt++) {
                int col = bn + wn + nt*8 + qid*2;
                float h0 = silu_f(accg[mt][nt][half*2+0]) * accu[mt][nt][half*2+0];
                float h1 = silu_f(accg[mt][nt][half*2+1]) * accu[mt][nt][half*2+1];
                __nv_bfloat16 a0 = __float2bfloat16(h0), a1 = __float2bfloat16(h1);
                *(__nv_bfloat162*)&Hh[rowoff + col] = __nv_bfloat162(a0, a1);
                *(__nv_bfloat162*)&Hl[rowoff + col] =
                    __nv_bfloat162(__float2bfloat16(h0 - __bfloat162float(a0)),
                                   __float2bfloat16(h1 - __bfloat162float(a1)));
            }
        }
    }
}

// ============ down GEMM, 128x128, 3-stage ============
// MODE 0: out = sgate[row]*acc (dense). MODE 1: atomicAdd(out[tok], pair_w*acc)
template<int MODE>
__global__ __launch_bounds__(256) void gemm_down(
    const __nv_bfloat16* __restrict__ Ah, const __nv_bfloat16* __restrict__ Al,
    const __nv_bfloat16* __restrict__ Bh, const __nv_bfloat16* __restrict__ Bl,
    float* __restrict__ out, int K)
{
    extern __shared__ char smem[];
    int tid = threadIdx.x;
    int bm = blockIdx.x * 128;
    int cnt = T_TOK, segoff = 0;
    if (MODE == 1) {
        int e = blockIdx.z;
        cnt = g_cnt[e]; segoff = g_off[e];
        if (bm >= cnt) return;
        size_t eo = (size_t)e * (size_t)HDIM * (size_t)K;
        Bh += eo; Bl += eo;
    }
    int bn = blockIdx.y * 128;
    uint32_t sbase = smem_u32(smem);
    int rowA = segoff + bm, rowAmax = segoff + cnt - 1;
    int NC = K / BK;

    auto stage_load = [&](uint32_t tb, int k0) {
        cp_tile128_clamp(tb,            Ah, rowA, rowAmax, K, k0, tid);
        cp_tile128_clamp(tb +   B_TILE, Al, rowA, rowAmax, K, k0, tid);
        cp_tile128(tb + 2*B_TILE, Bh, bn, K, k0, tid);
        cp_tile128(tb + 3*B_TILE, Bl, bn, K, k0, tid);
    };
    stage_load(sbase, 0);              CP_COMMIT();
    stage_load(sbase + STAGE_DN, BK);  CP_COMMIT();

    int lane = tid & 31, wid = tid >> 5;
    int wm = (wid >> 2) * 64, wn = (wid & 3) * 32;
    int lrow = lane & 15;
    int lcolb = (lane >> 4) * 16;

    float acc[4][4][4] = {};

    for (int c = 0; c < NC; c++) {
        if (c + 2 < NC) {
            stage_load(sbase + ((c + 2) % 3) * STAGE_DN, (c + 2) * BK);
            CP_COMMIT();
            CP_WAIT(2);
        } else if (c + 1 < NC) {
            CP_WAIT(1);
        } else {
            CP_WAIT(0);
        }
        __syncthreads();

        uint32_t tb = sbase + (c % 3) * STAGE_DN;
        uint32_t sAh = tb, sAl = tb + B_TILE;
        uint32_t sBh = tb + 2*B_TILE, sBl = tb + 3*B_TILE;

        #pragma unroll
        for (int kt = 0; kt < 4; kt++) {
            uint32_t cb = kt*32 + lcolb;
            uint32_t a_h[4][4], a_l[4][4], b_h[2][4], b_l[2][4];
            #pragma unroll
            for (int mt = 0; mt < 4; mt++) {
                uint32_t off = (uint32_t)(wm + mt*16 + lrow)*144 + cb;
                LDMX4(a_h[mt], sAh + off);
                LDMX4(a_l[mt], sAl + off);
            }
            #pragma unroll
            for (int p = 0; p < 2; p++) {
                uint32_t off = (uint32_t)(wn + p*16 + lrow)*144 + cb;
                LDMX4(b_h[p], sBh + off);
                LDMX4(b_l[p], sBl + off);
            }
            #pragma unroll
            for (int mt = 0; mt < 4; mt++)
                #pragma unroll
                for (int nt = 0; nt < 4; nt++) {
                    int p = nt >> 1, s = nt & 1;
                    MMA_BF16(acc[mt][nt], a_h[mt], b_h[p][s], b_h[p][s+2]);
                    MMA_BF16(acc[mt][nt], a_h[mt], b_l[p][s], b_l[p][s+2]);
                    MMA_BF16(acc[mt][nt], a_l[mt], b_h[p][s], b_h[p][s+2]);
                }
        }
        __syncthreads();
    }

    int groupID = lane >> 2, qid = lane & 3;
    #pragma unroll
    for (int mt = 0; mt < 4; mt++) {
        #pragma unroll
        for (int half = 0; half < 2; half++) {
            int lr = bm + wm + mt*16 + groupID + half*8;
            if (lr >= cnt) continue;
            #pragma unroll
            for (int nt = 0; nt < 4; nt++) {
                int col = bn + wn + nt*8 + qid*2;
                float v0 = acc[mt][nt][half*2 + 0];
                float v1 = acc[mt][nt][half*2 + 1];
                if (MODE == 0) {
                    float s = g_sgate[lr];
                    *(float2*)&out[(size_t)lr*HDIM + col] = make_float2(s*v0, s*v1);
                } else {
                    int p = segoff + lr;
                    int tok = g_pair_tok[p];
                    float w = g_pair_w[p];
                    atomicAdd(&out[(size_t)tok*HDIM + col],     w*v0);
                    atomicAdd(&out[(size_t)tok*HDIM + col + 1], w*v1);
                }
            }
        }
    }
}

// ---------------- conversion kernels ----------------
__global__ void split_kernel(const float* __restrict__ src, __nv_bfloat16* __restrict__ hi,
                             __nv_bfloat16* __restrict__ lo, long n4) {
    long i = blockIdx.x*(long)blockDim.x + threadIdx.x;
    if (i >= n4) return;
    float4 v = ((const float4*)src)[i];
    __nv_bfloat16 h0 = __float2bfloat16(v.x), h1 = __float2bfloat16(v.y);
    __nv_bfloat16 h2 = __float2bfloat16(v.z), h3 = __float2bfloat16(v.w);
    __nv_bfloat162* H = (__nv_bfloat162*)(hi + 4*i);
    __nv_bfloat162* L = (__nv_bfloat162*)(lo + 4*i);
    H[0] = __nv_bfloat162(h0, h1); H[1] = __nv_bfloat162(h2, h3);
    L[0] = __nv_bfloat162(__float2bfloat16(v.x - __bfloat162float(h0)),
                          __float2bfloat16(v.y - __bfloat162float(h1)));
    L[1] = __nv_bfloat162(__float2bfloat16(v.z - __bfloat162float(h2)),
                          __float2bfloat16(v.w - __bfloat162float(h3)));
}

__global__ void gather_split_kernel(const float* __restrict__ x) {
    int i = blockIdx.x*blockDim.x + threadIdx.x;
    const int n4 = NPAIR * (HDIM/4);
    if (i >= n4) return;
    int p = i / (HDIM/4), c4 = i % (HDIM/4);
    int tok = g_pair_tok[p];
    float4 v = *(const float4*)(x + (size_t)tok*HDIM + c4*4);
    size_t o = (size_t)p*HDIM + c4*4;
    __nv_bfloat16 h0 = __float2bfloat16(v.x), h1 = __float2bfloat16(v.y);
    __nv_bfloat16 h2 = __float2bfloat16(v.z), h3 = __float2bfloat16(v.w);
    ((__nv_bfloat162*)(g_xg_h + o))[0] = __nv_bfloat162(h0, h1);
    ((__nv_bfloat162*)(g_xg_h + o))[1] = __nv_bfloat162(h2, h3);
    ((__nv_bfloat162*)(g_xg_l + o))[0] = __nv_bfloat162(__float2bfloat16(v.x - __bfloat162float(h0)),
                                                        __float2bfloat16(v.y - __bfloat162float(h1)));
    ((__nv_bfloat162*)(g_xg_l + o))[1] = __nv_bfloat162(__float2bfloat16(v.z - __bfloat162float(h2)),
                                                        __float2bfloat16(v.w - __bfloat162float(h3)));
}

// ---------------- router ----------------
__global__ void zero_kernel() {
    int i = threadIdx.x;
    if (i < NEXP) { g_cnt[i] = 0; g_fill[i] = 0; }
}
__global__ void router_kernel(const float* __restrict__ x,
                              const float* __restrict__ gate_w,
                              const float* __restrict__ sgate_w) {
    int t = blockIdx.x;
    int w = threadIdx.x >> 5, lane = threadIdx.x & 31;
    __shared__ float logits[9];
    const float* xr = x + (size_t)t * HDIM;
    const float* wr = (w < 8) ? (gate_w + (size_t)w * HDIM) : sgate_w;
    float s = 0.f;
    for (int k = lane; k < HDIM; k += 32) s += xr[k] * wr[k];
    #pragma unroll
    for (int o = 16; o; o >>= 1) s += __shfl_xor_sync(0xffffffffu, s, o);
    if (lane == 0) logits[w] = s;
    __syncthreads();
    if (threadIdx.x == 0) {
        float mx = logits[0];
        #pragma unroll
        for (int e = 1; e < NEXP; e++) mx = fmaxf(mx, logits[e]);
        float p[NEXP], sum = 0.f;
        #pragma unroll
        for (int e = 0; e < NEXP; e++) { p[e] = expf(logits[e] - mx); sum += p[e]; }
        #pragma unroll
        for (int e = 0; e < NEXP; e++) p[e] /= sum;
        int i0 = 0; float v0 = p[0];
        #pragma unroll
        for (int e = 1; e < NEXP; e++) if (p[e] > v0) { v0 = p[e]; i0 = e; }
        int i1 = -1; float v1 = -1.f;
        #pragma unroll
        for (int e = 0; e < NEXP; e++) if (e != i0 && p[e] > v1) { v1 = p[e]; i1 = e; }
        float inv = 1.f / (v0 + v1);
        g_top_i[t*2+0] = i0; g_top_w[t*2+0] = v0 * inv;
        g_top_i[t*2+1] = i1; g_top_w[t*2+1] = v1 * inv;
        atomicAdd(&g_cnt[i0], 1);
        atomicAdd(&g_cnt[i1], 1);
        g_sgate[t] = 1.f / (1.f + expf(-logits[8]));
    }
}
__global__ void scan_kernel() {
    if (threadIdx.x == 0) {
        int o = 0;
        for (int e = 0; e < NEXP; e++) { g_off[e] = o; o += g_cnt[e]; }
    }
}
__global__ void scatter_kernel() {
    int t = blockIdx.x * blockDim.x + threadIdx.x;
    if (t >= T_TOK) return;
    #pragma unroll
    for (int k = 0; k < TOPK; k++) {
        int e = g_top_i[t*2+k];
        int pos = g_off[e] + atomicAdd(&g_fill[e], 1);
        g_pair_tok[pos] = t;
        g_pair_w[pos]   = g_top_w[t*2+k];
    }
}

// ---------------- launch ----------------
static void* sym(const void* s) { void* p = nullptr; cudaGetSymbolAddress(&p, s); return p; }

extern "C" void kernel_launch(void* const* d_in, const int* in_sizes, int n_in,
                              void* d_out, int out_size) {
    const float* x     = (const float*)d_in[0];
    const float* gatew = (const float*)d_in[1];
    const float* w1    = (const float*)d_in[2];
    const float* w2    = (const float*)d_in[3];
    const float* sgu   = (const float*)d_in[4];
    const float* sdown = (const float*)d_in[5];
    const float* sgw   = (const float*)d_in[6];
    float* out = (float*)d_out;

    cudaFuncSetAttribute(gemm_gu<false>, cudaFuncAttributeMaxDynamicSharedMemorySize, SMEM_GU);
    cudaFuncSetAttribute(gemm_gu<true>,  cudaFuncAttributeMaxDynamicSharedMemorySize, SMEM_GU);
    cudaFuncSetAttribute(gemm_down<0>,   cudaFuncAttributeMaxDynamicSharedMemorySize, SMEM_DN);
    cudaFuncSetAttribute(gemm_down<1>,   cudaFuncAttributeMaxDynamicSharedMemorySize, SMEM_DN);

    __nv_bfloat16 *xh = (__nv_bfloat16*)sym(g_x_h),  *xl = (__nv_bfloat16*)sym(g_x_l);
    __nv_bfloat16 *guh= (__nv_bfloat16*)sym(g_sgu_h),*gul= (__nv_bfloat16*)sym(g_sgu_l);
    __nv_bfloat16 *dnh= (__nv_bfloat16*)sym(g_sdn_h),*dnl= (__nv_bfloat16*)sym(g_sdn_l);
    __nv_bfloat16 *w1h= (__nv_bfloat16*)sym(g_w1_h), *w1l= (__nv_bfloat16*)sym(g_w1_l);
    __nv_bfloat16 *w2h= (__nv_bfloat16*)sym(g_w2_h), *w2l= (__nv_bfloat16*)sym(g_w2_l);
    __nv_bfloat16 *hsh= (__nv_bfloat16*)sym(g_hsh_h),*hsl= (__nv_bfloat16*)sym(g_hsh_l);
    __nv_bfloat16 *xgh= (__nv_bfloat16*)sym(g_xg_h), *xgl= (__nv_bfloat16*)sym(g_xg_l);
    __nv_bfloat16 *heh= (__nv_bfloat16*)sym(g_he_h), *hel= (__nv_bfloat16*)sym(g_he_l);

    zero_kernel<<<1, 32>>>();
    router_kernel<<<T_TOK, 288>>>(x, gatew, sgw);
    scan_kernel<<<1, 32>>>();
    scatter_kernel<<<(T_TOK + 255) / 256, 256>>>();

    auto spl = [&](const float* s, __nv_bfloat16* h, __nv_bfloat16* l, long n) {
        long n4 = n / 4;
        split_kernel<<<(unsigned)((n4 + 255) / 256), 256>>>(s, h, l, n4);
    };
    spl(x,     xh,  xl,  (long)T_TOK*HDIM);
    spl(sgu,   guh, gul, (long)2*ISH*HDIM);
    spl(sdown, dnh, dnl, (long)HDIM*ISH);
    spl(w1,    w1h, w1l, (long)NEXP*2*IMOE*HDIM);
    spl(w2,    w2h, w2l, (long)NEXP*HDIM*IMOE);
    gather_split_kernel<<<(NPAIR*(HDIM/4) + 255) / 256, 256>>>(x);

    // shared expert: paired gate_up (fused silu+split) -> down (sigmoid-gated dense write)
    gemm_gu<false><<<dim3(T_TOK/64, ISH/128), 256, SMEM_GU>>>(
        xh, xl, guh, gul, hsh, hsl, HDIM, ISH);
    gemm_down<0><<<dim3(T_TOK/128, HDIM/128), 256, SMEM_DN>>>(
        hsh, hsl, dnh, dnl, out, ISH);

    // routed experts: paired gathered gate_up -> weighted down scatter-add
    gemm_gu<true><<<dim3(T_TOK/64, IMOE/128, NEXP), 256, SMEM_GU>>>(
        xgh, xgl, w1h, w1l, heh, hel, HDIM, IMOE);
    gemm_down<1><<<dim3(T_TOK/128, HDIM/128, NEXP), 256, SMEM_DN>>>(
        heh, hel, w2h, w2l, out, IMOE);
}